// round 12
// baseline (speedup 1.0000x reference)
#include <cuda_runtime.h>

#define Tn 128
#define Bn 8
#define En 256
#define Hn 512
#define G4 2048
#define NB2 128
#define NT2 288        // 8 compute warps + 1 act warp
#define WSTR 516       // 512 + pad -> 16B-aligned rows
typedef unsigned long long ull;

// ---------------- device scratch ----------------
__device__ float g_xs[Tn * Bn * G4];   // emb@Wih_s + b_s, [(t*8+b)*2048 + col]
__device__ float g_xt[Tn * Bn * G4];   // emb@Wih_t + b_t
__device__ float4 g_hc[2][NB2][16];    // tagged h chunks {h0, h1, 0, tagbits}
__device__ unsigned int g_cnt;         // cold end-barrier counter (reset by GEMM)

// ---------------- helpers ----------------
__device__ __forceinline__ ull fma2(ull a, ull b, ull c) {
    ull d;
    asm("fma.rn.f32x2 %0, %1, %2, %3;" : "=l"(d) : "l"(a), "l"(b), "l"(c));
    return d;
}
__device__ __forceinline__ float2 up2(ull a) {
    float2 f;
    asm("mov.b64 {%0, %1}, %2;" : "=f"(f.x), "=f"(f.y) : "l"(a));
    return f;
}
__device__ __forceinline__ float rcpa(float x) {
    float r;
    asm("rcp.approx.f32 %0, %1;" : "=f"(r) : "f"(x));
    return r;
}
__device__ __forceinline__ float sigm(float x)   { return rcpa(1.f + __expf(-x)); }
__device__ __forceinline__ float tanh_f(float x) { return 1.f - 2.f * rcpa(__expf(2.f * x) + 1.f); }

__device__ __forceinline__ float4 ld_rel4(const float4* p) {
    float4 v;
    asm volatile("ld.relaxed.gpu.global.v4.f32 {%0,%1,%2,%3}, [%4];"
                 : "=f"(v.x), "=f"(v.y), "=f"(v.z), "=f"(v.w) : "l"(p) : "memory");
    return v;
}
__device__ __forceinline__ void st_rel4(float4* p, float4 v) {
    asm volatile("st.relaxed.gpu.global.v4.f32 [%0], {%1,%2,%3,%4};"
                 :: "l"(p), "f"(v.x), "f"(v.y), "f"(v.z), "f"(v.w) : "memory");
}

// ---------------- kernel 1: gathered input GEMM (both matrices via z) ----------------
__global__ void __launch_bounds__(256) input_gemm(const int* __restrict__ tokens,
                                                  const float* __restrict__ etab,
                                                  const float* __restrict__ W0,
                                                  const float* __restrict__ bias0,
                                                  const float* __restrict__ W1,
                                                  const float* __restrict__ bias1) {
    __shared__ float As[16][128];
    __shared__ float Bs[16][128];
    const int which = blockIdx.z;
    const float* W    = which ? W1 : W0;
    const float* bias = which ? bias1 : bias0;
    float* outp = which ? g_xt : g_xs;

    if (blockIdx.x == 0 && blockIdx.y == 0 && blockIdx.z == 0 && threadIdx.x == 0)
        g_cnt = 0u;

    const int m0 = blockIdx.y * 128;
    const int n0 = blockIdx.x * 128;
    const int tid = threadIdx.x;
    const int tr = tid >> 4, tc = tid & 15;

    float acc[8][8];
#pragma unroll
    for (int i = 0; i < 8; i++)
#pragma unroll
        for (int j = 0; j < 8; j++) acc[i][j] = 0.f;

    const int mA0 = tid >> 2;
    const int mA1 = (tid + 256) >> 2;
    const int kq0 = tid & 3;
    const int gm0 = m0 + mA0, gm1 = m0 + mA1;
    const long tok0 = tokens[(gm0 & 7) * Tn + (gm0 >> 3)];
    const long tok1 = tokens[(gm1 & 7) * Tn + (gm1 >> 3)];

    const int kb = tid >> 5;
    const int nq = tid & 31;

    for (int k0 = 0; k0 < En; k0 += 16) {
        float4 a0 = *(const float4*)&etab[tok0 * En + k0 + kq0 * 4];
        float4 a1 = *(const float4*)&etab[tok1 * En + k0 + kq0 * 4];
        As[kq0 * 4 + 0][mA0] = a0.x; As[kq0 * 4 + 1][mA0] = a0.y;
        As[kq0 * 4 + 2][mA0] = a0.z; As[kq0 * 4 + 3][mA0] = a0.w;
        As[kq0 * 4 + 0][mA1] = a1.x; As[kq0 * 4 + 1][mA1] = a1.y;
        As[kq0 * 4 + 2][mA1] = a1.z; As[kq0 * 4 + 3][mA1] = a1.w;

        *(float4*)&Bs[kb][nq * 4]     = *(const float4*)&W[(k0 + kb) * G4 + n0 + nq * 4];
        *(float4*)&Bs[kb + 8][nq * 4] = *(const float4*)&W[(k0 + kb + 8) * G4 + n0 + nq * 4];
        __syncthreads();

#pragma unroll
        for (int k = 0; k < 16; k++) {
            float av[8], bv[8];
            *(float4*)&av[0] = *(const float4*)&As[k][tr * 4];
            *(float4*)&av[4] = *(const float4*)&As[k][64 + tr * 4];
            *(float4*)&bv[0] = *(const float4*)&Bs[k][tc * 4];
            *(float4*)&bv[4] = *(const float4*)&Bs[k][64 + tc * 4];
#pragma unroll
            for (int i = 0; i < 8; i++)
#pragma unroll
                for (int j = 0; j < 8; j++) acc[i][j] += av[i] * bv[j];
        }
        __syncthreads();
    }

#pragma unroll
    for (int i = 0; i < 8; i++) {
        int m = m0 + ((i < 4) ? (tr * 4 + i) : (64 + tr * 4 + i - 4));
#pragma unroll
        for (int jh = 0; jh < 2; jh++) {
            int n = n0 + tc * 4 + jh * 64;
            float4 v;
            v.x = acc[i][jh * 4 + 0] + __ldg(&bias[n + 0]);
            v.y = acc[i][jh * 4 + 1] + __ldg(&bias[n + 1]);
            v.z = acc[i][jh * 4 + 2] + __ldg(&bias[n + 2]);
            v.w = acc[i][jh * 4 + 3] + __ldg(&bias[n + 3]);
            *(float4*)&outp[(long)m * G4 + n] = v;
        }
    }
}

// ---------------- kernel 2: persistent dual-LSTM, tagged-chunk exchange ----------------
// 128 blocks x 288 threads. Block bl owns h-units [bl*4, bl*4+4) => 16 gate cols.
// Chunk ci of producer p holds {h[b][p*4+q*2], h[b][p*4+q*2+1], 0, tag}, b=ci>>1, q=ci&1.
// consume (tid<256): thread handles producer p=tid>>1, half s=tid&1 (one 128B line).
// stage1 (tid<256): kg=tid>>4 (32-k slice), c=tid&15 (gate col); warp w's k-range
//                   [w*64,w*64+64) is exactly what it consumed -> __syncwarp only.
// stage2 (tid<128): c2=tid>>3, b2=tid&7.  act: warp 8 (tid 256..287) only.
__global__ void __launch_bounds__(NT2) lstm_kernel(const float* __restrict__ Whh_s,
                                                   const float* __restrict__ Whh_t,
                                                   const float* __restrict__ Wmh_t,
                                                   float* __restrict__ out) {
    extern __shared__ float sm[];
    float* wstage = sm;                    // [16][WSTR] weight staging
    float* hs     = wstage + 16 * WSTR;    // [8][WSTR]  current h
    float* redb   = hs + 8 * WSTR;         // [2][16][128] partials (step-parity buffered)
    float* prebuf = redb + 2 * 2048;       // [128] pre-activations
    float* hsnew  = prebuf + 128;          // [32]  new h staging

    const int tid = threadIdx.x;
    const int bl  = blockIdx.x;
    const int kg  = tid >> 4, c  = tid & 15;   // stage-1 (tid<256)
    const int c2  = tid >> 3, b2 = tid & 7;    // stage-2 (tid<128)
    const int col2 = (c2 >> 2) * Hn + bl * 4 + (c2 & 3);
    const int krot = (kg & 1) << 2;
    const int p = tid >> 1, s = tid & 1;       // consume (tid<256)
    const int atid = tid - 256;                // act-warp lane

    ull wreg[16];
    float creg = 0.f;   // c-state (act warp)

    auto stageW = [&](const float* W) {
        __syncthreads();
        for (int i = tid; i < 16 * Hn; i += NT2) {
            int cc = i & 15, k = i >> 4;
            int cl = (cc >> 2) * Hn + bl * 4 + (cc & 3);
            wstage[cc * WSTR + k] = W[(long)k * G4 + cl];
        }
        __syncthreads();
        if (tid < 256) {
#pragma unroll
            for (int i = 0; i < 16; i++)
                wreg[i] = *(const ull*)(wstage + c * WSTR + kg * 32 + 2 * i);
        }
    };

    // poll own half-line: lead chunk first, then batch-verify the rest
    auto consume = [&](int par, unsigned tag) {
        if (tid < 256) {
            const float4* base = &g_hc[par][p][s * 8];
            float4 v;
            do { v = ld_rel4(base); } while (__float_as_uint(v.w) != tag);
            {
                int b = s * 4, q = 0;
                *(float2*)&hs[b * WSTR + p * 4 + q * 2] = make_float2(v.x, v.y);
            }
            unsigned need = 0xFEu;
            while (need) {
#pragma unroll
                for (int i = 1; i < 8; i++) {
                    if (need & (1u << i)) {
                        float4 w = ld_rel4(base + i);
                        if (__float_as_uint(w.w) == tag) {
                            int b = s * 4 + (i >> 1), q = i & 1;
                            *(float2*)&hs[b * WSTR + p * 4 + q * 2] = make_float2(w.x, w.y);
                            need &= ~(1u << i);
                        }
                    }
                }
            }
        }
        __syncwarp();
    };

    auto stage1 = [&](float* red) {
        if (tid < 256) {
            float part[8];
#pragma unroll
            for (int b = 0; b < 8; b++) {
                const float* hb = hs + b * WSTR + kg * 32;
                ull a0 = 0ull, a1 = 0ull;
#pragma unroll
                for (int kq = 0; kq < 8; kq++) {
                    int kk = (kq + krot) & 7;
                    ulonglong2 hv = *(const ulonglong2*)(hb + kk * 4);
                    a0 = fma2(hv.x, wreg[2 * kk], a0);
                    a1 = fma2(hv.y, wreg[2 * kk + 1], a1);
                }
                float2 f0 = up2(a0), f1 = up2(a1);
                part[b] = (f0.x + f1.x) + (f0.y + f1.y);
            }
            *(float4*)&red[kg * 128 + c * 8]     = make_float4(part[0], part[1], part[2], part[3]);
            *(float4*)&red[kg * 128 + c * 8 + 4] = make_float4(part[4], part[5], part[6], part[7]);
        }
    };
    auto stage2 = [&](const float* red, float xv) {   // tid<128
        float pa = xv;
#pragma unroll
        for (int g = 0; g < 16; g++) pa += red[g * 128 + tid];
        return pa;
    };

    auto do_step = [&](const float* xbase, float rcv, int t,
                       int rpar, unsigned rtag, int wpar, unsigned wtag,
                       float* outp, float* redp) {
        float xv = 0.f;
        if (tid < 128) xv = __ldcg(&xbase[(long)(t * Bn + b2) * G4 + col2]);
        consume(rpar, rtag);
        stage1(redp);
        __syncthreads();
        if (tid < 128) prebuf[tid] = stage2(redp, xv + rcv);
        __syncthreads();
        if (tid >= 256) {   // act warp
            const int bb = atid >> 2, j = atid & 3;
            float iv = prebuf[(0  + j) * 8 + bb];
            float fv = prebuf[(4  + j) * 8 + bb];
            float gv = prebuf[(8  + j) * 8 + bb];
            float ov = prebuf[(12 + j) * 8 + bb];
            float cn = sigm(fv) * creg + sigm(iv) * tanh_f(gv);
            float hn = sigm(ov) * tanh_f(cn);
            creg = cn;
            hsnew[bb * 4 + j] = hn;
            __syncwarp();
            if (atid < 16) {   // one STG.128: 16 tagged chunks, committed together
                int b = atid >> 1, q = atid & 1;
                float4 ch = make_float4(hsnew[b * 4 + q * 2], hsnew[b * 4 + q * 2 + 1],
                                        0.f, __uint_as_float(wtag));
                st_rel4(&g_hc[wpar][bl][atid], ch);
            }
            if (atid < 8 && outp) {
                float4 v = *(const float4*)&hsnew[atid * 4];
                __stcg((float4*)&outp[(long)(atid * Tn + t) * Hn + bl * 4], v);
            }
        }
    };

    // ---- init: publish h(0)=0 with tag 1 (parity 1); stage shared weights ----
    if (tid < 16)
        st_rel4(&g_hc[1][bl][tid], make_float4(0.f, 0.f, 0.f, __uint_as_float(1u)));
    stageW(Whh_s);

    // ---- shared LSTM (attention is identity: softmax over the broadcast axis of
    //      h_shared sums to 1, so Rt == h_last, constant). step t: consume round
    //      t+1 (parity (t+1)&1), produce round t+2 (parity t&1). ----
    for (int t = 0; t < Tn; t++)
        do_step(g_xs, 0.f, t, (t + 1) & 1, (unsigned)(t + 1), t & 1,
                (unsigned)(t + 2), nullptr, redb + (t & 1) * 2048);

    // ---- h_last = round 129 (parity 1); rc = h_last @ Wmh_t ----
    consume(1, 129u);
    stageW(Wmh_t);
    stage1(redb);
    __syncthreads();
    float rcv = (tid < 128) ? stage2(redb, 0.f) : 0.f;
    stageW(Whh_t);          // leading syncthreads protects red reads above
    creg = 0.f;
    // publish task zero-state: round 130 (parity 0). Overwrite of round 128 is safe:
    // consuming round 129 from every block implies each finished reading round 128.
    if (tid < 16)
        st_rel4(&g_hc[0][bl][tid], make_float4(0.f, 0.f, 0.f, __uint_as_float(130u)));

    // ---- task LSTM: step t consumes round 130+t, produces 131+t ----
    for (int t = 0; t < Tn; t++)
        do_step(g_xt, rcv, t, t & 1, (unsigned)(130 + t), (t + 1) & 1,
                (unsigned)(131 + t), out, redb + (t & 1) * 2048);

    // ---- end: cold barrier, then zero own tag chunks for the next graph replay ----
    __syncthreads();
    if (tid == 0) {
        asm volatile("red.release.gpu.global.add.u32 [%0], 1;" :: "l"(&g_cnt) : "memory");
        unsigned v;
        do {
            asm volatile("ld.relaxed.gpu.global.u32 %0, [%1];"
                         : "=r"(v) : "l"(&g_cnt) : "memory");
        } while (v < (unsigned)NB2);
    }
    __syncthreads();
    if (tid < 16) {
        st_rel4(&g_hc[0][bl][tid], make_float4(0.f, 0.f, 0.f, 0.f));
        st_rel4(&g_hc[1][bl][tid], make_float4(0.f, 0.f, 0.f, 0.f));
    }
}

// ---------------- launch ----------------
extern "C" void kernel_launch(void* const* d_in, const int* in_sizes, int n_in,
                              void* d_out, int out_size) {
    const int sh = (n_in == 14) ? 0 : 1;
    const int*   tokens = (const int*)d_in[0];
    const float* etab   = (const float*)d_in[2 - sh];
    const float* Wih_s  = (const float*)d_in[3 - sh];
    const float* Whh_s  = (const float*)d_in[4 - sh];
    const float* b_s    = (const float*)d_in[5 - sh];
    const float* Wih_t  = (const float*)d_in[10 - sh];
    const float* Whh_t  = (const float*)d_in[11 - sh];
    const float* Wmh_t  = (const float*)d_in[12 - sh];
    const float* b_t    = (const float*)d_in[13 - sh];
    float* out = (float*)d_out;

    const int smem2 = (16 * WSTR + 8 * WSTR + 2 * 2048 + 128 + 32) * (int)sizeof(float);
    cudaFuncSetAttribute(lstm_kernel, cudaFuncAttributeMaxDynamicSharedMemorySize, smem2);

    dim3 gg(G4 / 128, (Tn * Bn) / 128, 2);  // (16, 8, 2)
    input_gemm<<<gg, 256>>>(tokens, etab, Wih_s, b_s, Wih_t, b_t);
    lstm_kernel<<<NB2, NT2, smem2>>>(Whh_s, Whh_t, Wmh_t, out);
}

// round 13
// speedup vs baseline: 1.9729x; 1.9729x over previous
#include <cuda_runtime.h>

#define Tn 128
#define Bn 8
#define En 256
#define Hn 512
#define G4 2048
#define NB2 128
#define NT2 256
#define WSTR 516
typedef unsigned long long ull;

// ---------------- device scratch ----------------
__device__ float g_xs[Tn * Bn * G4];
__device__ float g_xt[Tn * Bn * G4];
__device__ float4 g_hslot[2][2][4][NB2];   // [team][parity][local batch][block]
__device__ unsigned int g_cnts[2 * 64];    // per-team counters, 256B apart

// ---------------- helpers ----------------
__device__ __forceinline__ ull fma2(ull a, ull b, ull c) {
    ull d;
    asm("fma.rn.f32x2 %0, %1, %2, %3;" : "=l"(d) : "l"(a), "l"(b), "l"(c));
    return d;
}
__device__ __forceinline__ float2 up2(ull a) {
    float2 f;
    asm("mov.b64 {%0, %1}, %2;" : "=f"(f.x), "=f"(f.y) : "l"(a));
    return f;
}
__device__ __forceinline__ float rcpa(float x) {
    float r;
    asm("rcp.approx.f32 %0, %1;" : "=f"(r) : "f"(x));
    return r;
}
__device__ __forceinline__ float sigm(float x)   { return rcpa(1.f + __expf(-x)); }
__device__ __forceinline__ float tanh_f(float x) { return 1.f - 2.f * rcpa(__expf(2.f * x) + 1.f); }
__device__ __forceinline__ float4 ld_rel4(const float4* p) {
    float4 v;
    asm volatile("ld.relaxed.gpu.global.v4.f32 {%0,%1,%2,%3}, [%4];"
                 : "=f"(v.x), "=f"(v.y), "=f"(v.z), "=f"(v.w) : "l"(p) : "memory");
    return v;
}
__device__ __forceinline__ void st_rel4(float4* p, float4 v) {
    asm volatile("st.relaxed.gpu.global.v4.f32 [%0], {%1,%2,%3,%4};"
                 :: "l"(p), "f"(v.x), "f"(v.y), "f"(v.z), "f"(v.w) : "memory");
}

// ---------------- kernel 1: gathered input GEMM ----------------
__global__ void __launch_bounds__(256) input_gemm(const int* __restrict__ tokens,
                                                  const float* __restrict__ etab,
                                                  const float* __restrict__ W0,
                                                  const float* __restrict__ bias0,
                                                  const float* __restrict__ W1,
                                                  const float* __restrict__ bias1) {
    __shared__ float As[16][128];
    __shared__ float Bs[16][128];
    const int which = blockIdx.z;
    const float* W    = which ? W1 : W0;
    const float* bias = which ? bias1 : bias0;
    float* outp = which ? g_xt : g_xs;

    if (blockIdx.x == 0 && blockIdx.y == 0 && blockIdx.z == 0 && threadIdx.x < 2)
        g_cnts[threadIdx.x * 64] = 0u;

    const int m0 = blockIdx.y * 128;
    const int n0 = blockIdx.x * 128;
    const int tid = threadIdx.x;
    const int tr = tid >> 4, tc = tid & 15;

    float acc[8][8];
#pragma unroll
    for (int i = 0; i < 8; i++)
#pragma unroll
        for (int j = 0; j < 8; j++) acc[i][j] = 0.f;

    const int mA0 = tid >> 2;
    const int mA1 = (tid + 256) >> 2;
    const int kq0 = tid & 3;
    const int gm0 = m0 + mA0, gm1 = m0 + mA1;
    const long tok0 = tokens[(gm0 & 7) * Tn + (gm0 >> 3)];
    const long tok1 = tokens[(gm1 & 7) * Tn + (gm1 >> 3)];
    const int kb = tid >> 5;
    const int nq = tid & 31;

    for (int k0 = 0; k0 < En; k0 += 16) {
        float4 a0 = *(const float4*)&etab[tok0 * En + k0 + kq0 * 4];
        float4 a1 = *(const float4*)&etab[tok1 * En + k0 + kq0 * 4];
        As[kq0 * 4 + 0][mA0] = a0.x; As[kq0 * 4 + 1][mA0] = a0.y;
        As[kq0 * 4 + 2][mA0] = a0.z; As[kq0 * 4 + 3][mA0] = a0.w;
        As[kq0 * 4 + 0][mA1] = a1.x; As[kq0 * 4 + 1][mA1] = a1.y;
        As[kq0 * 4 + 2][mA1] = a1.z; As[kq0 * 4 + 3][mA1] = a1.w;
        *(float4*)&Bs[kb][nq * 4]     = *(const float4*)&W[(k0 + kb) * G4 + n0 + nq * 4];
        *(float4*)&Bs[kb + 8][nq * 4] = *(const float4*)&W[(k0 + kb + 8) * G4 + n0 + nq * 4];
        __syncthreads();
#pragma unroll
        for (int k = 0; k < 16; k++) {
            float av[8], bv[8];
            *(float4*)&av[0] = *(const float4*)&As[k][tr * 4];
            *(float4*)&av[4] = *(const float4*)&As[k][64 + tr * 4];
            *(float4*)&bv[0] = *(const float4*)&Bs[k][tc * 4];
            *(float4*)&bv[4] = *(const float4*)&Bs[k][64 + tc * 4];
#pragma unroll
            for (int i = 0; i < 8; i++)
#pragma unroll
                for (int j = 0; j < 8; j++) acc[i][j] += av[i] * bv[j];
        }
        __syncthreads();
    }
#pragma unroll
    for (int i = 0; i < 8; i++) {
        int m = m0 + ((i < 4) ? (tr * 4 + i) : (64 + tr * 4 + i - 4));
#pragma unroll
        for (int jh = 0; jh < 2; jh++) {
            int n = n0 + tc * 4 + jh * 64;
            float4 v;
            v.x = acc[i][jh * 4 + 0] + __ldg(&bias[n + 0]);
            v.y = acc[i][jh * 4 + 1] + __ldg(&bias[n + 1]);
            v.z = acc[i][jh * 4 + 2] + __ldg(&bias[n + 2]);
            v.w = acc[i][jh * 4 + 3] + __ldg(&bias[n + 3]);
            *(float4*)&outp[(long)m * G4 + n] = v;
        }
    }
}

// ---------------- kernel 2: dual-LSTM, two independent batch-half teams ----------------
// Block bl owns h-units [bl*4,bl*4+4) => 16 gate cols (col = g*512 + bl*4 + u).
// Team h (tid h*128..h*128+127) handles batches h*4..h*4+3: own counter/slots/named bar.
// Rounds: publish #r has parity r&1. init h=0 -> round 1. shared step t: consume t+1,
// publish t+2. task zero -> round 130. task step t: consume 130+t, publish 131+t.
// Overwrite-safe: consuming r implies all published r implies all finished reading r-1.
__global__ void __launch_bounds__(NT2) lstm_kernel(const float* __restrict__ Whh_s,
                                                   const float* __restrict__ Whh_t,
                                                   const float* __restrict__ Wmh_t,
                                                   float* __restrict__ out) {
    extern __shared__ float sm[];
    float* wstA = sm;                   // Whh_s (init) then Whh_t
    float* wstB = wstA + 16 * WSTR;     // Wmh_t
    float* hs   = wstB + 16 * WSTR;     // [8][WSTR] current h (rows team-disjoint)
    float* red  = hs + 8 * WSTR;        // [2][512] per-team partials
    float* hsnew = red + 1024;          // [2][16]

    const int tid  = threadIdx.x;
    const int bl   = blockIdx.x;
    const int h    = tid >> 7;
    const int ttid = tid & 127;
    const int kg   = ttid >> 4;         // 0..7: 64-k slice
    const int c    = ttid & 15;         // gate col within block
    const int barid = 1 + h;
    const bool isact = (ttid < 16);
    const int abloc = ttid >> 2, au = ttid & 3;
    float* myred = red + h * 512;
    unsigned int* mycnt = &g_cnts[h * 64];

    ull wreg[32];
    float cstate = 0.f;
    float rcv[4] = {0.f, 0.f, 0.f, 0.f};
    float xg[4]  = {0.f, 0.f, 0.f, 0.f};

    auto teambar = [&]() { asm volatile("bar.sync %0, 128;" :: "r"(barid) : "memory"); };
    auto stage = [&](const float* W, float* dst) {
        for (int i = tid; i < 16 * Hn; i += NT2) {
            int cc = i & 15, k = i >> 4;
            dst[cc * WSTR + k] = W[(long)k * G4 + ((cc >> 2) * Hn + bl * 4 + (cc & 3))];
        }
    };
    auto loadreg = [&](const float* src) {
#pragma unroll
        for (int i = 0; i < 32; i++)
            wreg[i] = *(const ull*)(src + c * WSTR + kg * 64 + 2 * i);
    };
    auto consume = [&](int par, unsigned round) {
        if (ttid == 32) {
            unsigned tgt = 128u * round, v;
            do {
                asm volatile("ld.relaxed.gpu.global.u32 %0, [%1];"
                             : "=r"(v) : "l"(mycnt) : "memory");
            } while (v < tgt);
        }
        teambar();
        const int bload = ttid >> 5, j = ttid & 31;
        const int bg = h * 4 + bload;
#pragma unroll
        for (int i = 0; i < 4; i++) {
            float4 d = ld_rel4(&g_hslot[h][par][bload][j + 32 * i]);
            *(float4*)&hs[bg * WSTR + (j + 32 * i) * 4] = d;
        }
        teambar();
    };
    auto dot = [&]() {
#pragma unroll
        for (int bb = 0; bb < 4; bb++) {
            const float* hb = hs + (h * 4 + bb) * WSTR + kg * 64;
            ull a0 = 0ull, a1 = 0ull;
#pragma unroll
            for (int i = 0; i < 16; i++) {
                int kk = (i + ((kg & 1) << 3)) & 15;   // bank-phase rotation
                ulonglong2 hv = *(const ulonglong2*)(hb + kk * 4);
                a0 = fma2(hv.x, wreg[2 * kk], a0);
                a1 = fma2(hv.y, wreg[2 * kk + 1], a1);
            }
            float2 f0 = up2(a0), f1 = up2(a1);
            myred[kg * 64 + c * 4 + bb] = (f0.x + f1.x) + (f0.y + f1.y);
        }
    };
    auto prefx = [&](const float* xb, int t) {   // isact: 4 gate cols of (t, my batch)
        long base = (long)(t * Bn + (h * 4 + abloc)) * G4 + bl * 4 + au;
#pragma unroll
        for (int g = 0; g < 4; g++) xg[g] = __ldcg(xb + base + g * 512);
    };

    auto step = [&](const float* xb, int t, int rpar, unsigned rnd,
                    int wpar, bool dout) {
        consume(rpar, rnd);
        dot();
        teambar();
        if (isact) {
            float pg[4];
#pragma unroll
            for (int g = 0; g < 4; g++) {
                float s = xg[g] + rcv[g];
#pragma unroll
                for (int k2 = 0; k2 < 8; k2++)
                    s += myred[k2 * 64 + (g * 4 + au) * 4 + abloc];
                pg[g] = s;
            }
            float cn = sigm(pg[1]) * cstate + sigm(pg[0]) * tanh_f(pg[2]);
            float hn = sigm(pg[3]) * tanh_f(cn);
            cstate = cn;
            hsnew[h * 16 + abloc * 4 + au] = hn;
            __syncwarp(0xffffu);
            if (ttid == 0) {
                float4 v0 = *(const float4*)&hsnew[h * 16 + 0];
                float4 v1 = *(const float4*)&hsnew[h * 16 + 4];
                float4 v2 = *(const float4*)&hsnew[h * 16 + 8];
                float4 v3 = *(const float4*)&hsnew[h * 16 + 12];
                st_rel4(&g_hslot[h][wpar][0][bl], v0);
                st_rel4(&g_hslot[h][wpar][1][bl], v1);
                st_rel4(&g_hslot[h][wpar][2][bl], v2);
                st_rel4(&g_hslot[h][wpar][3][bl], v3);
                asm volatile("red.release.gpu.global.add.u32 [%0], 1;"
                             :: "l"(mycnt) : "memory");
                if (dout) {
                    __stcg((float4*)&out[(long)((h * 4 + 0) * Tn + t) * Hn + bl * 4], v0);
                    __stcg((float4*)&out[(long)((h * 4 + 1) * Tn + t) * Hn + bl * 4], v1);
                    __stcg((float4*)&out[(long)((h * 4 + 2) * Tn + t) * Hn + bl * 4], v2);
                    __stcg((float4*)&out[(long)((h * 4 + 3) * Tn + t) * Hn + bl * 4], v3);
                }
            }
            prefx(xb, (t + 1) & (Tn - 1));
        }
    };

    // ---- init ----
    stage(Whh_s, wstA);
    __syncthreads();
    loadreg(wstA);                 // wreg <- Whh_s
    __syncthreads();
    stage(Whh_t, wstA);            // keep Whh_t, Wmh_t in smem for later
    stage(Wmh_t, wstB);
    __syncthreads();
    if (ttid == 0) {               // publish h(0)=0 as round 1 (counters reset by GEMM)
        float4 z = make_float4(0.f, 0.f, 0.f, 0.f);
#pragma unroll
        for (int bb = 0; bb < 4; bb++) st_rel4(&g_hslot[h][1][bb][bl], z);
        asm volatile("red.release.gpu.global.add.u32 [%0], 1;" :: "l"(mycnt) : "memory");
    }
    if (isact) prefx(g_xs, 0);

    // ---- shared LSTM (attention is identity: softmax over the broadcast axis of
    //      h_shared sums to 1, so Rt == h_last[b], constant per batch) ----
    for (int t = 0; t < Tn; t++)
        step(g_xs, t, (t + 1) & 1, (unsigned)(t + 1), t & 1, false);

    // ---- transition (per team): h_last = round 129 (parity 1) ----
    consume(1, 129u);
#pragma unroll
    for (int bb = 0; bb < 4; bb++) {       // rc partials = h_last[b] @ Wmh (smem)
        const float* hb = hs + (h * 4 + bb) * WSTR + kg * 64;
        const float* wb = wstB + c * WSTR + kg * 64;
        float s = 0.f;
#pragma unroll 8
        for (int i = 0; i < 64; i++) s += hb[i] * wb[i];
        myred[kg * 64 + c * 4 + bb] = s;
    }
    teambar();
    if (isact) {
#pragma unroll
        for (int g = 0; g < 4; g++) {
            float s = 0.f;
#pragma unroll
            for (int k2 = 0; k2 < 8; k2++)
                s += myred[k2 * 64 + (g * 4 + au) * 4 + abloc];
            rcv[g] = s;
        }
        cstate = 0.f;
    }
    loadreg(wstA);                 // wreg <- Whh_t
    if (ttid == 0) {               // task zero-state: round 130 (parity 0)
        float4 z = make_float4(0.f, 0.f, 0.f, 0.f);
#pragma unroll
        for (int bb = 0; bb < 4; bb++) st_rel4(&g_hslot[h][0][bb][bl], z);
        asm volatile("red.release.gpu.global.add.u32 [%0], 1;" :: "l"(mycnt) : "memory");
    }
    if (isact) prefx(g_xt, 0);
    teambar();                     // myred/rcv reads done before task dots overwrite

    // ---- task LSTM, writing output ----
    for (int t = 0; t < Tn; t++)
        step(g_xt, t, t & 1, (unsigned)(130 + t), (t + 1) & 1, true);
}

// ---------------- launch ----------------
extern "C" void kernel_launch(void* const* d_in, const int* in_sizes, int n_in,
                              void* d_out, int out_size) {
    const int sh = (n_in == 14) ? 0 : 1;
    const int*   tokens = (const int*)d_in[0];
    const float* etab   = (const float*)d_in[2 - sh];
    const float* Wih_s  = (const float*)d_in[3 - sh];
    const float* Whh_s  = (const float*)d_in[4 - sh];
    const float* b_s    = (const float*)d_in[5 - sh];
    const float* Wih_t  = (const float*)d_in[10 - sh];
    const float* Whh_t  = (const float*)d_in[11 - sh];
    const float* Wmh_t  = (const float*)d_in[12 - sh];
    const float* b_t    = (const float*)d_in[13 - sh];
    float* out = (float*)d_out;

    const int smem2 = (16 * WSTR * 2 + 8 * WSTR + 1024 + 32) * (int)sizeof(float);
    cudaFuncSetAttribute(lstm_kernel, cudaFuncAttributeMaxDynamicSharedMemorySize, smem2);

    dim3 gg(G4 / 128, (Tn * Bn) / 128, 2);
    input_gemm<<<gg, 256>>>(tokens, etab, Wih_s, b_s, Wih_t, b_t);
    lstm_kernel<<<NB2, NT2, smem2>>>(Whh_s, Whh_t, Wmh_t, out);
}